// round 12
// baseline (speedup 1.0000x reference)
#include <cuda_runtime.h>
#include <cstdint>

// SpectralConv2D fused kernel, R12: 2 batches per block with register prefetch
// (hide input DRAM latency behind batch-0 compute), halved per-block fixed cost.
//   out[b,l,f] = relu( sum_tap base[f,tap] * (enc[n]-dec[l]) * up[b,n] )
// Block = (tile kt: 2 output rows, batches b0 and b0+32).

#define B_    64
#define W_    32
#define C_    8
#define F_    64
#define O2_   30
#define L_    900
#define N_    1024
#define TILE  60

__constant__ int c_sel[9] = {0,1,1,2,0,1,2,2,0};
__constant__ int c_t  [9] = {0,0,1,0,1,2,1,2,2};
__constant__ int c_i  [9] = {0,0,0,1,1,1,2,2,2};
__constant__ int c_j  [9] = {0,1,2,0,1,2,0,1,2};

__device__ __forceinline__ uint64_t ffma2(uint64_t a, uint64_t b, uint64_t c) {
    uint64_t d;
    asm("fma.rn.f32x2 %0, %1, %2, %3;" : "=l"(d) : "l"(a), "l"(b), "l"(c));
    return d;
}
__device__ __forceinline__ uint64_t fmul2(uint64_t a, uint64_t b) {
    uint64_t d;
    asm("mul.rn.f32x2 %0, %1, %2;" : "=l"(d) : "l"(a), "l"(b));
    return d;
}
__device__ __forceinline__ float2 u64_as_f2(uint64_t v) {
    union { uint64_t u; float2 f; } cv; cv.u = v; return cv.f;
}

__global__ __launch_bounds__(256)
void spectral_fused_kernel(
    const float* __restrict__ inputs,      // (B, 32, 32, 8)
    const float* __restrict__ omega_diag,  // (F, 3)
    const float* __restrict__ omega_triu,  // (F*3)
    const float* __restrict__ omega_tril,  // (F*3)
    const float* __restrict__ lambda_in,   // (3)
    const float* __restrict__ lambda_out,  // (3)
    const float* __restrict__ use_encode,  // (N)
    const float* __restrict__ use_decode,  // (L)
    float* __restrict__ out)               // (B, L, F)
{
    __shared__ __align__(16) float up_s[128];       // 4 input rows x 32
    __shared__ __align__(16) float eu_s[128];       // enc*up
    __shared__ __align__(16) float dec_s[64];
    __shared__ __align__(16) float base_s[9 * F_];  // [tap][f]
    __shared__ __align__(16) float y_d[9 * 128];    // [tap][pos dup x2], pos 0..63

    const int tid = threadIdx.x;
    const int kt  = blockIdx.x;            // 0..14
    const int b0  = blockIdx.y;            // 0..31 -> batches b0, b0+32
    const int r0  = kt * 2;
    const int l0  = kt * TILE;

    // ---------------- prefetch BOTH batches' pixels (MLP=4) ----------------
    float4 va0, va1, vb0, vb1;
    float encv = 0.f;
    if (tid < 128) {
        int n = r0 * W_ + tid;             // rows r0..r0+3
        const float4* pa = (const float4*)(inputs + ((size_t)b0        * N_ + n) * C_);
        const float4* pb = (const float4*)(inputs + ((size_t)(b0 + 32) * N_ + n) * C_);
        va0 = pa[0]; va1 = pa[1];
        vb0 = pb[0]; vb1 = pb[1];
        encv = __ldg(&use_encode[n]);
    } else if (tid < 128 + TILE) {
        dec_s[tid - 128] = __ldg(&use_decode[l0 + tid - 128]);
    } else if (tid >= 184) {
        int k = tid - 184;                 // 0..71: zero-pad y positions 60..63
        y_d[(k >> 3) * 128 + 120 + (k & 7)] = 0.f;
    }

    // branchless base assembly: 576 entries over 256 threads, layout [tap][f]
    {
        const float* srcs[3] = { omega_diag, omega_triu, omega_tril };
        #pragma unroll
        for (int k = 0; k < 3; k++) {
            int idx = tid + k * 256;
            if (k < 2 || tid < 64) {
                int pp = idx >> 6;
                int f  = idx & 63;
                float w = __ldg(&srcs[c_sel[pp]][f * 3 + c_t[pp]]);
                float lam = __ldg(&lambda_in[c_i[pp]]) - __ldg(&lambda_out[c_j[pp]]);
                base_s[idx] = w * lam;
            }
        }
    }

    const int f4 = tid & 15;               // filter quad
    const int g  = tid >> 4;               // 0..15 -> positions g*4..g*4+3

    #pragma unroll
    for (int it = 0; it < 2; it++) {
        const int b = b0 + it * 32;

        // ---- Phase A-store: smem fill from prefetched regs ----
        if (tid < 128) {
            float4 v0 = it ? vb0 : va0;
            float4 v1 = it ? vb1 : va1;
            float m = (v0.x + v0.y + v0.z + v0.w + v1.x + v1.y + v1.z + v1.w) * 0.125f;
            up_s[tid] = m;
            eu_s[tid] = m * encv;
        }
        // barrier: (a) up_s/eu_s visible, (b) it=1: all warps done with C(it=0)
        // so y_d may be overwritten. base_s/dec_s/pad also covered at it=0.
        __syncthreads();

        // ---- Phase B: duplicated y, one thread per position ----
        if (tid < TILE) {
            float dec = dec_s[tid];
            int i0 = (tid >= 30) ? (tid + 2) : tid;    // orow*32 + ocol
            float2* yd = (float2*)y_d;                  // [tap*64 + pos]
            #pragma unroll
            for (int tap = 0; tap < 9; tap++) {
                const int off = (tap / 3) * 32 + (tap % 3);
                float v = eu_s[i0 + off] - dec * up_s[i0 + off];
                yd[tap * 64 + tid] = make_float2(v, v);
            }
        }
        __syncthreads();

        // ---- Phase C: 4 pos x 4 filters per thread, FFMA2 ----
        uint64_t acc[4][2];
        #pragma unroll
        for (int tap = 0; tap < 9; tap++) {
            ulonglong2 wv = *(const ulonglong2*)(base_s + tap * F_ + f4 * 4);
            const ulonglong2* yrow = (const ulonglong2*)(y_d + tap * 128 + g * 8);
            ulonglong2 y01 = yrow[0];
            ulonglong2 y23 = yrow[1];
            if (tap == 0) {
                acc[0][0] = fmul2(y01.x, wv.x); acc[0][1] = fmul2(y01.x, wv.y);
                acc[1][0] = fmul2(y01.y, wv.x); acc[1][1] = fmul2(y01.y, wv.y);
                acc[2][0] = fmul2(y23.x, wv.x); acc[2][1] = fmul2(y23.x, wv.y);
                acc[3][0] = fmul2(y23.y, wv.x); acc[3][1] = fmul2(y23.y, wv.y);
            } else {
                acc[0][0] = ffma2(y01.x, wv.x, acc[0][0]); acc[0][1] = ffma2(y01.x, wv.y, acc[0][1]);
                acc[1][0] = ffma2(y01.y, wv.x, acc[1][0]); acc[1][1] = ffma2(y01.y, wv.y, acc[1][1]);
                acc[2][0] = ffma2(y23.x, wv.x, acc[2][0]); acc[2][1] = ffma2(y23.x, wv.y, acc[2][1]);
                acc[3][0] = ffma2(y23.y, wv.x, acc[3][0]); acc[3][1] = ffma2(y23.y, wv.y, acc[3][1]);
            }
        }

        float* obase = out + ((size_t)b * L_ + l0 + g * 4) * F_ + f4 * 4;
        #pragma unroll
        for (int k = 0; k < 4; k++) {
            int pos = g * 4 + k;
            if (pos < TILE) {
                float2 a0 = u64_as_f2(acc[k][0]);
                float2 a1 = u64_as_f2(acc[k][1]);
                float4 o;
                o.x = fmaxf(a0.x, 0.f);
                o.y = fmaxf(a0.y, 0.f);
                o.z = fmaxf(a1.x, 0.f);
                o.w = fmaxf(a1.y, 0.f);
                *(float4*)(obase + k * F_) = o;
            }
        }
    }
}

extern "C" void kernel_launch(void* const* d_in, const int* in_sizes, int n_in,
                              void* d_out, int out_size) {
    (void)in_sizes; (void)n_in; (void)out_size;
    const float* inputs      = (const float*)d_in[0];
    const float* omega_diag  = (const float*)d_in[1];
    const float* omega_triu  = (const float*)d_in[2];
    const float* omega_tril  = (const float*)d_in[3];
    const float* lambda_in   = (const float*)d_in[4];
    const float* lambda_out  = (const float*)d_in[5];
    const float* use_encode  = (const float*)d_in[6];
    const float* use_decode  = (const float*)d_in[7];
    float* out = (float*)d_out;

    dim3 grid(L_ / TILE, B_ / 2);   // (15, 32) = 480 blocks, 2 batches each
    spectral_fused_kernel<<<grid, 256>>>(
        inputs, omega_diag, omega_triu, omega_tril,
        lambda_in, lambda_out, use_encode, use_decode, out);
}

// round 13
// speedup vs baseline: 1.0029x; 1.0029x over previous
#include <cuda_runtime.h>
#include <cstdint>

// SpectralConv2D fused kernel, R13: R11 shape + critical-path cuts:
//  - input LDG first instructions (early memory wait start)
//  - Phase B spread over 180 threads (3 taps each), 3x shorter serial section
//  - w preloaded to regs between barriers; Phase C = 2 LDS.128 + 8 FFMA2 / tap
//   out[b,l,f] = relu( sum_tap base[f,tap] * (enc[n]-dec[l]) * up[b,n] )

#define B_    64
#define W_    32
#define C_    8
#define F_    64
#define O2_   30
#define L_    900
#define N_    1024
#define TILE  60

__constant__ int c_sel[9] = {0,1,1,2,0,1,2,2,0};
__constant__ int c_t  [9] = {0,0,1,0,1,2,1,2,2};
__constant__ int c_i  [9] = {0,0,0,1,1,1,2,2,2};
__constant__ int c_j  [9] = {0,1,2,0,1,2,0,1,2};

__device__ __forceinline__ uint64_t ffma2(uint64_t a, uint64_t b, uint64_t c) {
    uint64_t d;
    asm("fma.rn.f32x2 %0, %1, %2, %3;" : "=l"(d) : "l"(a), "l"(b), "l"(c));
    return d;
}
__device__ __forceinline__ uint64_t fmul2(uint64_t a, uint64_t b) {
    uint64_t d;
    asm("mul.rn.f32x2 %0, %1, %2;" : "=l"(d) : "l"(a), "l"(b));
    return d;
}
__device__ __forceinline__ float2 u64_as_f2(uint64_t v) {
    union { uint64_t u; float2 f; } cv; cv.u = v; return cv.f;
}

__global__ __launch_bounds__(256)
void spectral_fused_kernel(
    const float* __restrict__ inputs,      // (B, 32, 32, 8)
    const float* __restrict__ omega_diag,  // (F, 3)
    const float* __restrict__ omega_triu,  // (F*3)
    const float* __restrict__ omega_tril,  // (F*3)
    const float* __restrict__ lambda_in,   // (3)
    const float* __restrict__ lambda_out,  // (3)
    const float* __restrict__ use_encode,  // (N)
    const float* __restrict__ use_decode,  // (L)
    float* __restrict__ out)               // (B, L, F)
{
    __shared__ __align__(16) float up_s[128];       // 4 input rows x 32
    __shared__ __align__(16) float eu_s[128];       // enc*up
    __shared__ __align__(16) float dec_s[64];
    __shared__ __align__(16) float base_s[9 * F_];  // [tap][f]
    __shared__ __align__(16) float y_d[9 * 128];    // [tap][pos dup x2], pos 0..63

    const int tid = threadIdx.x;

    // ---- FIRST: issue input loads (minimal ALU prefix, early mem-wait start) ----
    float4 v0, v1;
    float encv = 0.f;
    {
        // n = r0*W + tid for tid<128; harmless clamped load otherwise
        int n = blockIdx.x * 2 * W_ + (tid & 127);
        const float4* p = (const float4*)(inputs + ((size_t)blockIdx.y * N_ + n) * C_);
        v0 = p[0];
        v1 = p[1];
        encv = __ldg(&use_encode[n]);
    }

    const int kt  = blockIdx.x;            // 0..14
    const int b   = blockIdx.y;
    const int l0  = kt * TILE;

    // ---------------- Phase A: smem fill + dec + pad ----------------
    if (tid < 128) {
        float m = (v0.x + v0.y + v0.z + v0.w + v1.x + v1.y + v1.z + v1.w) * 0.125f;
        up_s[tid] = m;
        eu_s[tid] = m * encv;
    } else if (tid < 128 + TILE) {
        dec_s[tid - 128] = __ldg(&use_decode[l0 + tid - 128]);
    } else if (tid >= 184) {
        int k = tid - 184;                 // 0..71: zero-pad y positions 60..63
        y_d[(k >> 3) * 128 + 120 + (k & 7)] = 0.f;
    }

    // branchless base assembly: 576 entries over 256 threads, layout [tap][f]
    {
        const float* srcs[3] = { omega_diag, omega_triu, omega_tril };
        #pragma unroll
        for (int k = 0; k < 3; k++) {
            int idx = tid + k * 256;
            if (k < 2 || tid < 64) {
                int pp = idx >> 6;
                int f  = idx & 63;
                float w = __ldg(&srcs[c_sel[pp]][f * 3 + c_t[pp]]);
                float lam = __ldg(&lambda_in[c_i[pp]]) - __ldg(&lambda_out[c_j[pp]]);
                base_s[idx] = w * lam;
            }
        }
    }
    __syncthreads();

    // ---------------- Phase B: 180 threads, 3 taps each ----------------
    if (tid < 180) {
        int grp = (tid >= 120) ? 2 : (tid >= 60 ? 1 : 0);
        int pos = tid - grp * 60;          // 0..59
        float dec = dec_s[pos];
        int i0 = (pos >= 30) ? (pos + 2) : pos;    // orow*32 + ocol
        float2* yd = (float2*)y_d;                  // [tap*64 + pos]
        #pragma unroll
        for (int k = 0; k < 3; k++) {
            int tap = grp * 3 + k;
            const int off = (tap / 3) * 32 + (tap % 3);  // grp==tap/3 here
            float v = eu_s[i0 + off] - dec * up_s[i0 + off];
            yd[tap * 64 + pos] = make_float2(v, v);
        }
    }

    // ---- overlap Phase-B wait: preload w into registers (base_s final) ----
    const int f4 = tid & 15;               // filter quad
    const int g  = tid >> 4;               // 0..15 -> positions g*4..g*4+3
    ulonglong2 w[9];
    #pragma unroll
    for (int tap = 0; tap < 9; tap++)
        w[tap] = *(const ulonglong2*)(base_s + tap * F_ + f4 * 4);

    __syncthreads();

    // ---------------- Phase C: 4 pos x 4 filters per thread, FFMA2 ----------------
    uint64_t acc[4][2];
    #pragma unroll
    for (int tap = 0; tap < 9; tap++) {
        const ulonglong2* yrow = (const ulonglong2*)(y_d + tap * 128 + g * 8);
        ulonglong2 y01 = yrow[0];          // dup pairs for pos g*4, g*4+1
        ulonglong2 y23 = yrow[1];          // pos g*4+2, g*4+3
        if (tap == 0) {
            acc[0][0] = fmul2(y01.x, w[0].x); acc[0][1] = fmul2(y01.x, w[0].y);
            acc[1][0] = fmul2(y01.y, w[0].x); acc[1][1] = fmul2(y01.y, w[0].y);
            acc[2][0] = fmul2(y23.x, w[0].x); acc[2][1] = fmul2(y23.x, w[0].y);
            acc[3][0] = fmul2(y23.y, w[0].x); acc[3][1] = fmul2(y23.y, w[0].y);
        } else {
            acc[0][0] = ffma2(y01.x, w[tap].x, acc[0][0]); acc[0][1] = ffma2(y01.x, w[tap].y, acc[0][1]);
            acc[1][0] = ffma2(y01.y, w[tap].x, acc[1][0]); acc[1][1] = ffma2(y01.y, w[tap].y, acc[1][1]);
            acc[2][0] = ffma2(y23.x, w[tap].x, acc[2][0]); acc[2][1] = ffma2(y23.x, w[tap].y, acc[2][1]);
            acc[3][0] = ffma2(y23.y, w[tap].x, acc[3][0]); acc[3][1] = ffma2(y23.y, w[tap].y, acc[3][1]);
        }
    }

    float* obase = out + ((size_t)b * L_ + l0 + g * 4) * F_ + f4 * 4;
    #pragma unroll
    for (int k = 0; k < 4; k++) {
        int pos = g * 4 + k;
        if (pos < TILE) {
            float2 a0 = u64_as_f2(acc[k][0]);
            float2 a1 = u64_as_f2(acc[k][1]);
            float4 o;
            o.x = fmaxf(a0.x, 0.f);
            o.y = fmaxf(a0.y, 0.f);
            o.z = fmaxf(a1.x, 0.f);
            o.w = fmaxf(a1.y, 0.f);
            *(float4*)(obase + k * F_) = o;
        }
    }
}

extern "C" void kernel_launch(void* const* d_in, const int* in_sizes, int n_in,
                              void* d_out, int out_size) {
    (void)in_sizes; (void)n_in; (void)out_size;
    const float* inputs      = (const float*)d_in[0];
    const float* omega_diag  = (const float*)d_in[1];
    const float* omega_triu  = (const float*)d_in[2];
    const float* omega_tril  = (const float*)d_in[3];
    const float* lambda_in   = (const float*)d_in[4];
    const float* lambda_out  = (const float*)d_in[5];
    const float* use_encode  = (const float*)d_in[6];
    const float* use_decode  = (const float*)d_in[7];
    float* out = (float*)d_out;

    dim3 grid(L_ / TILE, B_);   // (15, 64) = 960 blocks
    spectral_fused_kernel<<<grid, 256>>>(
        inputs, omega_diag, omega_triu, omega_tril,
        lambda_in, lambda_out, use_encode, use_decode, out);
}